// round 4
// baseline (speedup 1.0000x reference)
#include <cuda_runtime.h>
#include <math.h>

#define Bsz 64
#define Tsz 2048
#define Dsz 256
#define Hsz 512
#define Gsz 2048
#define NB  128

typedef unsigned long long u64;

// ---- packed fp32x2 helpers (Blackwell FFMA2, PTX-only) ----
__device__ __forceinline__ u64 ffma2(u64 a, u64 b, u64 c) {
    u64 d;
    asm("fma.rn.f32x2 %0, %1, %2, %3;" : "=l"(d) : "l"(a), "l"(b), "l"(c));
    return d;
}
__device__ __forceinline__ u64 dup2(float x) {
    u64 d;
    asm("mov.b64 %0, {%1, %1};" : "=l"(d) : "r"(__float_as_uint(x)));
    return d;
}
__device__ __forceinline__ float lo2(u64 d) { return __int_as_float((int)(unsigned)(d & 0xffffffffu)); }
__device__ __forceinline__ float hi2(u64 d) { return __int_as_float((int)(unsigned)(d >> 32)); }

// Scratch (device globals)
__device__ float g_xw[(size_t)Tsz * Gsz * Bsz];    // [t][col][b]  1 GiB
__device__ float g_Up[64 * Hsz * 32];              // [cg][k][c]   4 MB
__device__ float g_h[2 * Hsz * Bsz];               // [parity][j][b]
__device__ unsigned g_bar;

__global__ void reset_bar_k() { g_bar = 0u; }

// g_Up[cg][k][c] = U[k][gate*512 + cg*8 + jj], c = gate*8 + jj  (32 cols per cg)
__global__ void pack_U_k(const float* __restrict__ U) {
    int idx = blockIdx.x * blockDim.x + threadIdx.x;   // 2^20 total
    int c  = idx & 31;
    int k  = (idx >> 5) & (Hsz - 1);
    int cg = idx >> 14;
    g_Up[idx] = U[k * Gsz + (c >> 3) * Hsz + cg * 8 + (c & 7)];
}

// xW GEMM with FFMA2: C[b][col] = sum_k x[b,t,k]*W[k,col] + bias[col] -> [t][col][b]
__global__ __launch_bounds__(256, 2) void gemm_xw_k(const float* __restrict__ x,
                                                    const float* __restrict__ W,
                                                    const float* __restrict__ bias) {
    const int t   = blockIdx.y;
    const int cb  = blockIdx.x;
    const int tid = threadIdx.x;
    __shared__ float As[32 * 68];
    __shared__ float Bs[32 * 132];
    const int b0 = (tid & 15) * 4;
    const int c0 = (tid >> 4) * 8;

    u64 acc[4][4];
    {
        ulonglong2 bb0 = *(const ulonglong2*)(bias + cb * 128 + c0);
        ulonglong2 bb1 = *(const ulonglong2*)(bias + cb * 128 + c0 + 4);
#pragma unroll
        for (int i = 0; i < 4; ++i) {
            acc[i][0] = bb0.x; acc[i][1] = bb0.y;
            acc[i][2] = bb1.x; acc[i][3] = bb1.y;
        }
    }
    const int arow = tid >> 3;
    const int af4  = tid & 7;
    const int wk   = tid >> 3;
    const int wc   = (tid & 7) * 16;

    for (int k0 = 0; k0 < Dsz; k0 += 32) {
#pragma unroll
        for (int pass = 0; pass < 2; ++pass) {
            int b = arow + pass * 32;
            float4 v = *(const float4*)(x + ((size_t)b * Tsz + t) * Dsz + k0 + af4 * 4);
            As[(af4 * 4 + 0) * 68 + b] = v.x;
            As[(af4 * 4 + 1) * 68 + b] = v.y;
            As[(af4 * 4 + 2) * 68 + b] = v.z;
            As[(af4 * 4 + 3) * 68 + b] = v.w;
        }
        const float* wp = W + (size_t)(k0 + wk) * Gsz + cb * 128 + wc;
        float4 w0 = ((const float4*)wp)[0];
        float4 w1 = ((const float4*)wp)[1];
        float4 w2 = ((const float4*)wp)[2];
        float4 w3 = ((const float4*)wp)[3];
        *(float4*)&Bs[wk * 132 + wc + 0]  = w0;
        *(float4*)&Bs[wk * 132 + wc + 4]  = w1;
        *(float4*)&Bs[wk * 132 + wc + 8]  = w2;
        *(float4*)&Bs[wk * 132 + wc + 12] = w3;
        __syncthreads();
#pragma unroll
        for (int kk = 0; kk < 32; ++kk) {
            float4 a = *(const float4*)&As[kk * 68 + b0];
            ulonglong2 u01 = *(const ulonglong2*)&Bs[kk * 132 + c0];
            ulonglong2 u23 = *(const ulonglong2*)&Bs[kk * 132 + c0 + 4];
            u64 a0 = dup2(a.x), a1 = dup2(a.y), a2 = dup2(a.z), a3 = dup2(a.w);
            acc[0][0] = ffma2(a0, u01.x, acc[0][0]);
            acc[1][0] = ffma2(a1, u01.x, acc[1][0]);
            acc[2][0] = ffma2(a2, u01.x, acc[2][0]);
            acc[3][0] = ffma2(a3, u01.x, acc[3][0]);
            acc[0][1] = ffma2(a0, u01.y, acc[0][1]);
            acc[1][1] = ffma2(a1, u01.y, acc[1][1]);
            acc[2][1] = ffma2(a2, u01.y, acc[2][1]);
            acc[3][1] = ffma2(a3, u01.y, acc[3][1]);
            acc[0][2] = ffma2(a0, u23.x, acc[0][2]);
            acc[1][2] = ffma2(a1, u23.x, acc[1][2]);
            acc[2][2] = ffma2(a2, u23.x, acc[2][2]);
            acc[3][2] = ffma2(a3, u23.x, acc[3][2]);
            acc[0][3] = ffma2(a0, u23.y, acc[0][3]);
            acc[1][3] = ffma2(a1, u23.y, acc[1][3]);
            acc[2][3] = ffma2(a2, u23.y, acc[2][3]);
            acc[3][3] = ffma2(a3, u23.y, acc[3][3]);
        }
        __syncthreads();
    }
#pragma unroll
    for (int jp = 0; jp < 4; ++jp) {
        float4 lo = make_float4(lo2(acc[0][jp]), lo2(acc[1][jp]), lo2(acc[2][jp]), lo2(acc[3][jp]));
        float4 hi = make_float4(hi2(acc[0][jp]), hi2(acc[1][jp]), hi2(acc[2][jp]), hi2(acc[3][jp]));
        size_t base = (size_t)t * Gsz + cb * 128;
        *(float4*)&g_xw[(base + c0 + 2 * jp) * 64 + b0]     = lo;
        *(float4*)&g_xw[(base + c0 + 2 * jp + 1) * 64 + b0] = hi;
    }
}

__device__ __forceinline__ void gsync(unsigned target) {
    __syncthreads();
    if (threadIdx.x == 0) {
        __threadfence();
        atomicAdd(&g_bar, 1u);
        while (*((volatile unsigned*)&g_bar) < target) { }
        __threadfence();
    }
    __syncthreads();
}

// Persistent recurrence — broadcast-h / register-U version.
// 128 CTAs = (b-half bh) x (64 col-groups cg: 8 hidden units = 32 gate cols).
// 256 threads = 8 warps; warp w owns k-range [64w, 64w+64); lane c (0..31) holds
// Ureg[64] = U[k][c] in registers (no U smem traffic, ever).
// Per k: 8x LDS.128 of the h row — all lanes same address = BROADCAST (free on
// crossbar) — then 16 FFMA2 into acc[16] (32 batches as fp32x2 pairs).
// Cross-warp reduce: 8 partials via coalesced [q][w][c] float4 smem layout.
// Smem: hs[512][32] (64KB, aliased by partials) + red[32][36].
#define REC_SMEM_FLOATS (16384 + 32 * 36)

__global__ __launch_bounds__(256, 1) void lstm_rec_k(float* __restrict__ out) {
    extern __shared__ float sm[];
    float* hs   = sm;            // [512][32] staged h (b-half)
    float* part = sm;            // alias after compute: float4 [q:8][w:8][c:32]
    float* red  = sm + 16384;    // [32c][36]

    const int n   = blockIdx.x;
    const int tid = threadIdx.x;
    const int bh  = n & 1;
    const int cg  = n >> 1;
    const int w   = tid >> 5;          // warp = K-range owner
    const int L   = tid & 31;          // lane = gate column c
    const int ub  = tid & 31;          // update role: batch within half
    const int ujj = tid >> 5;          // update role: hidden-within-cg 0..7
    const int jbase = cg * 8;

    // U slice into registers: Ureg[i] = U[k = 64w + i][c = L]
    float Ureg[64];
    {
        const float* Ub = g_Up + (size_t)cg * 16384 + (w * 64) * 32 + L;
#pragma unroll
        for (int i = 0; i < 64; ++i) Ureg[i] = Ub[i * 32];
    }

    // zero h parity 0 (this CTA's slice)
    g_h[(jbase + ujj) * 64 + bh * 32 + ub] = 0.0f;
    float creg = 0.0f, hreg = 0.0f;

    unsigned target = NB;
    gsync(target); target += NB;

    for (int step = 0; step < Tsz; ++step) {
        const int p = step & 1;
        const float* hsrc = g_h + p * (Hsz * Bsz) + bh * 32;

        // prefetch this thread's xW contribution (update role)
        float xg0 = __ldcs(&g_xw[((size_t)step * Gsz + 0 * Hsz + jbase + ujj) * 64 + bh * 32 + ub]);
        float xg1 = __ldcs(&g_xw[((size_t)step * Gsz + 1 * Hsz + jbase + ujj) * 64 + bh * 32 + ub]);
        float xg2 = __ldcs(&g_xw[((size_t)step * Gsz + 2 * Hsz + jbase + ujj) * 64 + bh * 32 + ub]);
        float xg3 = __ldcs(&g_xw[((size_t)step * Gsz + 3 * Hsz + jbase + ujj) * 64 + bh * 32 + ub]);

        // stage h: 512 rows x 32 floats; 16 float4 per thread (two batches of 8)
#pragma unroll
        for (int half = 0; half < 2; ++half) {
            float4 pv[8];
#pragma unroll
            for (int m = 0; m < 8; ++m) {
                int idx = tid + 256 * (half * 8 + m);
                int r = idx >> 3, q = idx & 7;
                pv[m] = __ldcg((const float4*)(hsrc + r * 64) + q);
            }
#pragma unroll
            for (int m = 0; m < 8; ++m) {
                int idx = tid + 256 * (half * 8 + m);
                int r = idx >> 3, q = idx & 7;
                *(float4*)&hs[r * 32 + q * 4] = pv[m];
            }
        }
        __syncthreads();

        // compute: acc[j] = fp32x2 partial gates for b-pair j, col L, k in warp range
        u64 acc[16];
#pragma unroll
        for (int j = 0; j < 16; ++j) acc[j] = 0ull;

        {
            const float* hrow = hs + (w * 64) * 32;
#pragma unroll
            for (int i = 0; i < 64; ++i) {
                u64 ud = dup2(Ureg[i]);
#pragma unroll
                for (int bp = 0; bp < 8; ++bp) {
                    ulonglong2 hp = *(const ulonglong2*)(hrow + i * 32 + bp * 4);
                    acc[2 * bp]     = ffma2(hp.x, ud, acc[2 * bp]);
                    acc[2 * bp + 1] = ffma2(hp.y, ud, acc[2 * bp + 1]);
                }
            }
        }
        __syncthreads();   // all warps done reading hs

        // partial store: float4 slot index (q*8 + w)*32 + L  (coalesced, conflict-free)
#pragma unroll
        for (int q = 0; q < 8; ++q)
            *(ulonglong2*)&part[(((q * 8) + w) * 32 + L) * 4] =
                make_ulonglong2(acc[2 * q], acc[2 * q + 1]);
        __syncthreads();

        // reduce over 8 warps: thread -> (q = tid>>5, c = tid&31)
        {
            const int rq = tid >> 5, rc = tid & 31;
            float4 s = *(const float4*)&part[((rq * 8 + 0) * 32 + rc) * 4];
#pragma unroll
            for (int ww = 1; ww < 8; ++ww) {
                float4 v = *(const float4*)&part[((rq * 8 + ww) * 32 + rc) * 4];
                s.x += v.x; s.y += v.y; s.z += v.z; s.w += v.w;
            }
            *(float4*)&red[rc * 36 + rq * 4] = s;
        }
        __syncthreads();

        // elementwise update: thread owns (b = ub, j = jbase + ujj)
        float v0 = red[(0 * 8 + ujj) * 36 + ub] + xg0;
        float v1 = red[(1 * 8 + ujj) * 36 + ub] + xg1;
        float v2 = red[(2 * 8 + ujj) * 36 + ub] + xg2;
        float v3 = red[(3 * 8 + ujj) * 36 + ub] + xg3;
        float ig = 1.0f / (1.0f + __expf(-v0));
        float fg = 1.0f / (1.0f + __expf(-v1));
        float gg = tanhf(v2);
        float og = 1.0f / (1.0f + __expf(-v3));
        creg = fg * creg + ig * gg;
        hreg = og * tanhf(creg);
        g_h[(p ^ 1) * (Hsz * Bsz) + (jbase + ujj) * 64 + bh * 32 + ub] = hreg;

        gsync(target); target += NB;
    }

    out[(bh * 32 + ub) * Hsz + jbase + ujj] = hreg;
    out[Bsz * Hsz + (bh * 32 + ub) * Hsz + jbase + ujj] = creg;
}

extern "C" void kernel_launch(void* const* d_in, const int* in_sizes, int n_in,
                              void* d_out, int out_size) {
    const float* x    = (const float*)d_in[0];
    const float* W    = (const float*)d_in[1];
    const float* U    = (const float*)d_in[2];
    const float* bias = (const float*)d_in[3];
    float* out = (float*)d_out;
    (void)in_sizes; (void)n_in; (void)out_size;

    static int smem_set = 0;
    if (!smem_set) {
        cudaFuncSetAttribute(lstm_rec_k, cudaFuncAttributeMaxDynamicSharedMemorySize,
                             REC_SMEM_FLOATS * 4);
        smem_set = 1;
    }

    pack_U_k<<<2048, 512>>>(U);
    dim3 g(16, Tsz);
    gemm_xw_k<<<g, 256>>>(x, W, bias);
    reset_bar_k<<<1, 1>>>();
    lstm_rec_k<<<NB, 256, REC_SMEM_FLOATS * 4>>>(out);
}

// round 5
// speedup vs baseline: 1.0647x; 1.0647x over previous
#include <cuda_runtime.h>
#include <math.h>

#define Bsz 64
#define Tsz 2048
#define Dsz 256
#define Hsz 512
#define Gsz 2048
#define NB  128
#define GRP 64

typedef unsigned long long u64;

// ---- packed fp32x2 helpers (Blackwell FFMA2/FADD2, PTX-only) ----
__device__ __forceinline__ u64 ffma2(u64 a, u64 b, u64 c) {
    u64 d;
    asm("fma.rn.f32x2 %0, %1, %2, %3;" : "=l"(d) : "l"(a), "l"(b), "l"(c));
    return d;
}
__device__ __forceinline__ u64 fadd2(u64 a, u64 b) {
    u64 d;
    asm("add.rn.f32x2 %0, %1, %2;" : "=l"(d) : "l"(a), "l"(b));
    return d;
}
__device__ __forceinline__ u64 dup2(float x) {
    u64 d;
    asm("mov.b64 %0, {%1, %1};" : "=l"(d) : "r"(__float_as_uint(x)));
    return d;
}
__device__ __forceinline__ float lo2(u64 d) { return __int_as_float((int)(unsigned)(d & 0xffffffffu)); }
__device__ __forceinline__ float hi2(u64 d) { return __int_as_float((int)(unsigned)(d >> 32)); }

// Scratch (device globals)
__device__ float g_xw[(size_t)Tsz * Gsz * Bsz];    // [t][col][b]  1 GiB
__device__ float g_Up[64 * Hsz * 32];              // [cg][k][c]   4 MB
__device__ float g_h[2 * Hsz * Bsz];               // [parity][j][b]
__device__ unsigned g_cnt[2][32];                  // per-group counter (padded line)
__device__ volatile unsigned g_flag[2][32];        // per-group release flag

__global__ void reset_bar_k() {
    g_cnt[0][0] = 0u; g_cnt[1][0] = 0u;
    g_flag[0][0] = 0u; g_flag[1][0] = 0u;
}

// g_Up[cg][k][c] = U[k][gate*512 + cg*8 + jj], c = gate*8 + jj  (32 cols per cg)
__global__ void pack_U_k(const float* __restrict__ U) {
    int idx = blockIdx.x * blockDim.x + threadIdx.x;   // 2^20 total
    int c  = idx & 31;
    int k  = (idx >> 5) & (Hsz - 1);
    int cg = idx >> 14;
    g_Up[idx] = U[k * Gsz + (c >> 3) * Hsz + cg * 8 + (c & 7)];
}

// xW GEMM with FFMA2: C[b][col] = sum_k x[b,t,k]*W[k,col] + bias[col] -> [t][col][b]
__global__ __launch_bounds__(256, 2) void gemm_xw_k(const float* __restrict__ x,
                                                    const float* __restrict__ W,
                                                    const float* __restrict__ bias) {
    const int t   = blockIdx.y;
    const int cb  = blockIdx.x;
    const int tid = threadIdx.x;
    __shared__ float As[32 * 68];
    __shared__ float Bs[32 * 132];
    const int b0 = (tid & 15) * 4;
    const int c0 = (tid >> 4) * 8;

    u64 acc[4][4];
    {
        ulonglong2 bb0 = *(const ulonglong2*)(bias + cb * 128 + c0);
        ulonglong2 bb1 = *(const ulonglong2*)(bias + cb * 128 + c0 + 4);
#pragma unroll
        for (int i = 0; i < 4; ++i) {
            acc[i][0] = bb0.x; acc[i][1] = bb0.y;
            acc[i][2] = bb1.x; acc[i][3] = bb1.y;
        }
    }
    const int arow = tid >> 3;
    const int af4  = tid & 7;
    const int wk   = tid >> 3;
    const int wc   = (tid & 7) * 16;

    for (int k0 = 0; k0 < Dsz; k0 += 32) {
#pragma unroll
        for (int pass = 0; pass < 2; ++pass) {
            int b = arow + pass * 32;
            float4 v = *(const float4*)(x + ((size_t)b * Tsz + t) * Dsz + k0 + af4 * 4);
            As[(af4 * 4 + 0) * 68 + b] = v.x;
            As[(af4 * 4 + 1) * 68 + b] = v.y;
            As[(af4 * 4 + 2) * 68 + b] = v.z;
            As[(af4 * 4 + 3) * 68 + b] = v.w;
        }
        const float* wp = W + (size_t)(k0 + wk) * Gsz + cb * 128 + wc;
        float4 w0 = ((const float4*)wp)[0];
        float4 w1 = ((const float4*)wp)[1];
        float4 w2 = ((const float4*)wp)[2];
        float4 w3 = ((const float4*)wp)[3];
        *(float4*)&Bs[wk * 132 + wc + 0]  = w0;
        *(float4*)&Bs[wk * 132 + wc + 4]  = w1;
        *(float4*)&Bs[wk * 132 + wc + 8]  = w2;
        *(float4*)&Bs[wk * 132 + wc + 12] = w3;
        __syncthreads();
#pragma unroll
        for (int kk = 0; kk < 32; ++kk) {
            float4 a = *(const float4*)&As[kk * 68 + b0];
            ulonglong2 u01 = *(const ulonglong2*)&Bs[kk * 132 + c0];
            ulonglong2 u23 = *(const ulonglong2*)&Bs[kk * 132 + c0 + 4];
            u64 a0 = dup2(a.x), a1 = dup2(a.y), a2 = dup2(a.z), a3 = dup2(a.w);
            acc[0][0] = ffma2(a0, u01.x, acc[0][0]);
            acc[1][0] = ffma2(a1, u01.x, acc[1][0]);
            acc[2][0] = ffma2(a2, u01.x, acc[2][0]);
            acc[3][0] = ffma2(a3, u01.x, acc[3][0]);
            acc[0][1] = ffma2(a0, u01.y, acc[0][1]);
            acc[1][1] = ffma2(a1, u01.y, acc[1][1]);
            acc[2][1] = ffma2(a2, u01.y, acc[2][1]);
            acc[3][1] = ffma2(a3, u01.y, acc[3][1]);
            acc[0][2] = ffma2(a0, u23.x, acc[0][2]);
            acc[1][2] = ffma2(a1, u23.x, acc[1][2]);
            acc[2][2] = ffma2(a2, u23.x, acc[2][2]);
            acc[3][2] = ffma2(a3, u23.x, acc[3][2]);
            acc[0][3] = ffma2(a0, u23.y, acc[0][3]);
            acc[1][3] = ffma2(a1, u23.y, acc[1][3]);
            acc[2][3] = ffma2(a2, u23.y, acc[2][3]);
            acc[3][3] = ffma2(a3, u23.y, acc[3][3]);
        }
        __syncthreads();
    }
#pragma unroll
    for (int jp = 0; jp < 4; ++jp) {
        float4 lo = make_float4(lo2(acc[0][jp]), lo2(acc[1][jp]), lo2(acc[2][jp]), lo2(acc[3][jp]));
        float4 hi = make_float4(hi2(acc[0][jp]), hi2(acc[1][jp]), hi2(acc[2][jp]), hi2(acc[3][jp]));
        size_t base = (size_t)t * Gsz + cb * 128;
        *(float4*)&g_xw[(base + c0 + 2 * jp) * 64 + b0]     = lo;
        *(float4*)&g_xw[(base + c0 + 2 * jp + 1) * 64 + b0] = hi;
    }
}

// ---- split group barrier (64 CTAs per group) ----
__device__ __forceinline__ void garrive(int g, unsigned target) {
    __syncthreads();                    // all threads' h writes done
    if (threadIdx.x == 0) {
        __threadfence();                // release h to GPU scope
        unsigned old = atomicAdd(&g_cnt[g][0], 1u);
        if (old == target - 1u) g_flag[g][0] = target;
    }
}
__device__ __forceinline__ void gwait(int g, unsigned target) {
    if (threadIdx.x == 0) {
        while (g_flag[g][0] < target) { }
        __threadfence();                // acquire
    }
    __syncthreads();
}

// Persistent recurrence — R3-style tiles, minimal glue.
// 128 CTAs = (b-half bh) x (64 col-groups cg: 8 hidden units = 32 gate cols).
// 256 threads = 8 warps; warp w owns k in [64w, 64w+64). Lane: b0=(L&3)*8,
// c0=(L>>2)*4 -> thread tile 8 batches x 4 cols (16 FFMA2/k). Per k: 3 LDS
// (all conflict-free/merged) + 4 MOV + 16 FFMA2.
// Smem: Us[512][32] resident (64KB), hs[512][32] staged (64KB; partials
// [8w][32c][32b] alias it), red[32][36].
#define REC_SMEM_FLOATS (16384 + 16384 + 32 * 36)

__global__ __launch_bounds__(256, 1) void lstm_rec_k(float* __restrict__ out) {
    extern __shared__ float sm[];
    float* Us   = sm;            // [512][32]
    float* hs   = sm + 16384;    // [512][32]
    float* part = sm + 16384;    // alias: [w][c][b] = w*1024 + c*32 + b
    float* red  = sm + 32768;    // [32][36]

    const int n   = blockIdx.x;
    const int tid = threadIdx.x;
    const int bh  = n & 1;
    const int cg  = n >> 1;
    const int w   = tid >> 5;
    const int L   = tid & 31;
    const int b0  = (L & 3) * 8;
    const int c0  = (L >> 2) * 4;
    const int ub  = tid & 31;          // update role: batch within half
    const int ujj = tid >> 5;          // update role: hidden-within-cg 0..7
    const int jbase = cg * 8;

    // resident U slice [512][32]
    {
        const float4* Usrc = (const float4*)(g_Up + (size_t)cg * 16384);
        float4* Udst = (float4*)Us;
        for (int i = tid; i < 4096; i += 256) Udst[i] = Usrc[i];
    }

    // zero h parity 0 (this CTA's slice)
    g_h[(jbase + ujj) * 64 + bh * 32 + ub] = 0.0f;
    float creg = 0.0f, hreg = 0.0f;

    unsigned target = GRP;
    garrive(bh, target);

    for (int step = 0; step < Tsz; ++step) {
        const int p = step & 1;
        const float* hsrc = g_h + p * (Hsz * Bsz) + bh * 32;

        // xW loads issued BEFORE the spin (in flight during barrier wait)
        const size_t xbase = (size_t)step * Gsz;
        float xg0 = __ldcs(&g_xw[(xbase + 0 * Hsz + jbase + ujj) * 64 + bh * 32 + ub]);
        float xg1 = __ldcs(&g_xw[(xbase + 1 * Hsz + jbase + ujj) * 64 + bh * 32 + ub]);
        float xg2 = __ldcs(&g_xw[(xbase + 2 * Hsz + jbase + ujj) * 64 + bh * 32 + ub]);
        float xg3 = __ldcs(&g_xw[(xbase + 3 * Hsz + jbase + ujj) * 64 + bh * 32 + ub]);

        gwait(bh, target);
        target += GRP;

        // one-shot stage: 512 rows x 32 floats (64KB), 16 float4 per thread
#pragma unroll
        for (int half = 0; half < 2; ++half) {
            float4 pv[8];
#pragma unroll
            for (int m = 0; m < 8; ++m) {
                int idx = tid + 256 * (half * 8 + m);
                int r = idx >> 3, q = idx & 7;
                pv[m] = __ldcg((const float4*)(hsrc + r * 64) + q);
            }
#pragma unroll
            for (int m = 0; m < 8; ++m) {
                int idx = tid + 256 * (half * 8 + m);
                int r = idx >> 3, q = idx & 7;
                *(float4*)&hs[r * 32 + q * 4] = pv[m];
            }
        }
        __syncthreads();

        // compute: warp w covers k in [64w,64w+64); acc[j*4+i]: col c0+j, b-pair i
        u64 acc[16];
#pragma unroll
        for (int j = 0; j < 16; ++j) acc[j] = 0ull;
        {
            const int kb = w * 64;
#pragma unroll 16
            for (int i = 0; i < 64; ++i) {
                const int k = kb + i;
                ulonglong2 hA = *(const ulonglong2*)&hs[k * 32 + b0];
                ulonglong2 hB = *(const ulonglong2*)&hs[k * 32 + b0 + 4];
                float4 uq = *(const float4*)&Us[k * 32 + c0];
                u64 u0 = dup2(uq.x), u1 = dup2(uq.y), u2 = dup2(uq.z), u3 = dup2(uq.w);
                acc[0]  = ffma2(hA.x, u0, acc[0]);
                acc[1]  = ffma2(hA.y, u0, acc[1]);
                acc[2]  = ffma2(hB.x, u0, acc[2]);
                acc[3]  = ffma2(hB.y, u0, acc[3]);
                acc[4]  = ffma2(hA.x, u1, acc[4]);
                acc[5]  = ffma2(hA.y, u1, acc[5]);
                acc[6]  = ffma2(hB.x, u1, acc[6]);
                acc[7]  = ffma2(hB.y, u1, acc[7]);
                acc[8]  = ffma2(hA.x, u2, acc[8]);
                acc[9]  = ffma2(hA.y, u2, acc[9]);
                acc[10] = ffma2(hB.x, u2, acc[10]);
                acc[11] = ffma2(hB.y, u2, acc[11]);
                acc[12] = ffma2(hA.x, u3, acc[12]);
                acc[13] = ffma2(hA.y, u3, acc[13]);
                acc[14] = ffma2(hB.x, u3, acc[14]);
                acc[15] = ffma2(hB.y, u3, acc[15]);
            }
        }
        __syncthreads();   // all warps done reading hs (part aliases hs)

        // per-warp partial tile [32c][32b]
#pragma unroll
        for (int j = 0; j < 4; ++j) {
            float* pp = part + w * 1024 + (c0 + j) * 32 + b0;
            *(ulonglong2*)pp       = make_ulonglong2(acc[4 * j + 0], acc[4 * j + 1]);
            *(ulonglong2*)(pp + 4) = make_ulonglong2(acc[4 * j + 2], acc[4 * j + 3]);
        }
        __syncthreads();

        // reduce over 8 warps: thread -> col c=tid>>3, b-quad q=tid&7
        {
            const int rc = tid >> 3, rq = (tid & 7) * 4;
            ulonglong2 s = *(const ulonglong2*)&part[rc * 32 + rq];
#pragma unroll
            for (int ww = 1; ww < 8; ++ww) {
                ulonglong2 v = *(const ulonglong2*)&part[ww * 1024 + rc * 32 + rq];
                s.x = fadd2(s.x, v.x);
                s.y = fadd2(s.y, v.y);
            }
            *(ulonglong2*)&red[rc * 36 + rq] = s;
        }
        __syncthreads();

        // elementwise update: thread owns (b = ub, j = jbase + ujj)
        float v0 = red[(0 * 8 + ujj) * 36 + ub] + xg0;
        float v1 = red[(1 * 8 + ujj) * 36 + ub] + xg1;
        float v2 = red[(2 * 8 + ujj) * 36 + ub] + xg2;
        float v3 = red[(3 * 8 + ujj) * 36 + ub] + xg3;
        float ig = 1.0f / (1.0f + __expf(-v0));
        float fg = 1.0f / (1.0f + __expf(-v1));
        float gg = tanhf(v2);
        float og = 1.0f / (1.0f + __expf(-v3));
        creg = fg * creg + ig * gg;
        hreg = og * tanhf(creg);
        g_h[(p ^ 1) * (Hsz * Bsz) + (jbase + ujj) * 64 + bh * 32 + ub] = hreg;

        garrive(bh, target);
    }

    out[(bh * 32 + ub) * Hsz + jbase + ujj] = hreg;
    out[Bsz * Hsz + (bh * 32 + ub) * Hsz + jbase + ujj] = creg;
}

extern "C" void kernel_launch(void* const* d_in, const int* in_sizes, int n_in,
                              void* d_out, int out_size) {
    const float* x    = (const float*)d_in[0];
    const float* W    = (const float*)d_in[1];
    const float* U    = (const float*)d_in[2];
    const float* bias = (const float*)d_in[3];
    float* out = (float*)d_out;
    (void)in_sizes; (void)n_in; (void)out_size;

    static int smem_set = 0;
    if (!smem_set) {
        cudaFuncSetAttribute(lstm_rec_k, cudaFuncAttributeMaxDynamicSharedMemorySize,
                             REC_SMEM_FLOATS * 4);
        smem_set = 1;
    }

    pack_U_k<<<2048, 512>>>(U);
    dim3 g(16, Tsz);
    gemm_xw_k<<<g, 256>>>(x, W, bias);
    reset_bar_k<<<1, 1>>>();
    lstm_rec_k<<<NB, 256, REC_SMEM_FLOATS * 4>>>(out);
}